// round 8
// baseline (speedup 1.0000x reference)
#include <cuda_runtime.h>
#include <cstdint>
#include <cstddef>

#define Bz 64
#define Sz 2048
#define Hz 256

typedef unsigned long long ull;

// ---------------- scratch (static device arrays: no runtime allocation) -----
__device__ float g_A0[(size_t)Bz * Sz * Hz];   // x@w_h0 + b_h0, [B,S,H]
__device__ float g_H1[(size_t)Bz * Sz * Hz];   // h1 states,     [B,S,H]
__device__ float g_h0r[2][Bz * Hz];            // h0 state ring  [slot][b*256+k]
__device__ float g_h1r[2][Bz * Hz];            // h1 state ring

// packed fp32x2 ops (sm_100+)
__device__ __forceinline__ ull ffma2(ull a, ull b, ull c) {
    ull d;
    asm("fma.rn.f32x2 %0, %1, %2, %3;" : "=l"(d) : "l"(a), "l"(b), "l"(c));
    return d;
}
__device__ __forceinline__ ull dupf(float x) {
    ull r;
    asm("mov.b64 %0, {%1, %1};" : "=l"(r) : "f"(x));
    return r;
}
__device__ __forceinline__ float2 asf2(ull u) {
    float2 f;
    asm("mov.b64 {%0, %1}, %2;" : "=f"(f.x), "=f"(f.y) : "l"(u));
    return f;
}

// ---------------- init: zero state rings each launch (determinism) ----------
__global__ void init_k() {
    int i = blockIdx.x * blockDim.x + threadIdx.x;
    if (i < 2 * Bz * Hz) {
        ((float*)g_h0r)[i] = 0.f;
        ((float*)g_h1r)[i] = 0.f;
    }
}

// ---------------- C[M,256] = A[M,256] @ W[256,256] + bias (f32x2 math) ------
__global__ __launch_bounds__(256) void gemm256(const float* __restrict__ A,
                                               const float* __restrict__ W,
                                               const float* __restrict__ bias,
                                               float* __restrict__ C) {
    __shared__ float As[64][68];
    __shared__ float Ws[64][64];
    const int tid = threadIdx.x;
    const int tm = tid >> 4, tn = tid & 15;
    const int m0 = blockIdx.x * 64, n0 = blockIdx.y * 64;

    ull acc[4][2];
#pragma unroll
    for (int i = 0; i < 4; ++i) { acc[i][0] = 0ull; acc[i][1] = 0ull; }
    const float4 bv = *(const float4*)&bias[n0 + tn * 4];

    for (int k0 = 0; k0 < 256; k0 += 64) {
#pragma unroll
        for (int f = 0; f < 4; ++f) {
            int v  = tid + f * 256;
            int r0 = v >> 4;
            int c4 = (v & 15) << 2;
            *(float4*)&As[r0][c4] = *(const float4*)&A[(size_t)(m0 + r0) * 256 + k0 + c4];
            *(float4*)&Ws[r0][c4] = *(const float4*)&W[(size_t)(k0 + r0) * 256 + n0 + c4];
        }
        __syncthreads();
#pragma unroll 8
        for (int kk = 0; kk < 64; ++kk) {
            ulonglong2 wv = *(const ulonglong2*)&Ws[kk][tn * 4];
#pragma unroll
            for (int i = 0; i < 4; ++i) {
                ull d = dupf(As[tm * 4 + i][kk]);
                acc[i][0] = ffma2(d, wv.x, acc[i][0]);
                acc[i][1] = ffma2(d, wv.y, acc[i][1]);
            }
        }
        __syncthreads();
    }
#pragma unroll
    for (int i = 0; i < 4; ++i) {
        float2 lo = asf2(acc[i][0]), hi = asf2(acc[i][1]);
        float4 o = make_float4(lo.x + bv.x, lo.y + bv.y, hi.x + bv.z, hi.y + bv.w);
        *(float4*)&C[(size_t)(m0 + tm * 4 + i) * 256 + n0 + tn * 4] = o;
    }
}

// ---------------- persistent clustered recurrence: 4 rows / cluster ---------
// 16 clusters x 4 CTAs x 512 threads. Cluster c owns batch rows [4c, 4c+4);
// CTA rank r owns columns [64r, 64r+64) of u_h0/w_h1/u_h1 (in REGISTERS).
// Per step: stage 4-row states (L2 rings -> dup smem), three FMA passes
// (one per matrix, 4 packed accumulators each), k-split reduce, epilogue,
// ONE cluster barrier. Pipeline: G0 h0n[t]; G1 a1[t-1] (local); G2 h1n[t-2].

#define HS_S 12            // hs row stride (floats): 8 used + 4 pad, 48B align
#define PS_S 264           // ps row stride (floats): 256 used + 8 pad

__global__ void __cluster_dims__(4, 1, 1) __launch_bounds__(512, 1)
rnn_k(const float* __restrict__ u_h0, const float* __restrict__ w_h1,
      const float* __restrict__ u_h1, const float* __restrict__ b_h1,
      float* __restrict__ hf) {
    extern __shared__ __align__(16) float sm[];
    float* hs0 = sm;                        // 256*12  dup h0n  [k][b0b0..b3b3]
    float* hs1 = sm + 256 * HS_S;           // 256*12  dup h1n
    float* ps  = sm + 2 * 256 * HS_S;       // 3*16*264 k-split partials
    float* a1s = ps + 3 * 16 * PS_S;        // 2*256 local a1 ring

    const int tid  = threadIdx.x;
    const int ks   = tid >> 5;                // warp id = k-split (16)
    const int lane = tid & 31;                // lane = col-pair
    const int bg   = (blockIdx.x >> 2) * 4;   // first batch row of cluster
    const int j0   = (blockIdx.x & 3) * 64;   // first col of this CTA

    // ---- persistent weights in registers: 3 x 16 packed col-pairs ----
    ull wr0[16], wr1[16], wr2[16];
#pragma unroll
    for (int kk = 0; kk < 16; ++kk) {
        size_t o = (size_t)(ks * 16 + kk) * 256 + j0 + lane * 2;
        wr0[kk] = __ldg((const ull*)&u_h0[o]);
        wr1[kk] = __ldg((const ull*)&w_h1[o]);
        wr2[kk] = __ldg((const ull*)&u_h1[o]);
    }

    // stage identity: warp ks stages its own k-slice; lane -> (k, row-pair)
    const int skk = lane & 15;
    const int srp = lane >> 4;                // rows {2srp, 2srp+1}
    const int sk  = ks * 16 + skk;

    // reduce/epilogue identity: egrp 0:h0n 1:h1n 2:a1 3:idle; pair outputs
    const int eo   = tid;
    const int egrp = eo >> 7;
    const int eidx = eo & 127;
    const int eb   = eidx >> 5;               // row 0..3
    const int ejp  = eidx & 31;                // col pair
    const int co   = j0 + 2 * ejp;
    ull bias2 = 0;
    if (egrp == 2) bias2 = *(const ull*)&b_h1[co];
    const ull one2 = dupf(1.0f);

    for (int t = 0; t < Sz + 2; ++t) {
        // A0 prefetch for G0 epilogue (hidden behind the step)
        ull a0p = 0;
        if (egrp == 0 && t < Sz)
            a0p = __ldcg((const ull*)&g_A0[((size_t)(bg + eb) * Sz + t) * 256 + co]);

        // ---- stage 4-row states from L2 rings into duplicated smem ----
        {
            const int sl = (t + 1) & 1;       // h0n[t-1] / h1n[t-3] parity
            const float* r0 = g_h0r[sl] + sk;
            const float* r1 = g_h1r[sl] + sk;
            float h0a = __ldcg(r0 + (bg + 2 * srp) * 256);
            float h0b = __ldcg(r0 + (bg + 2 * srp + 1) * 256);
            float h1a = __ldcg(r1 + (bg + 2 * srp) * 256);
            float h1b = __ldcg(r1 + (bg + 2 * srp + 1) * 256);
            *(ull*)&hs0[sk * HS_S + 4 * srp]     = dupf(h0a);
            *(ull*)&hs0[sk * HS_S + 4 * srp + 2] = dupf(h0b);
            *(ull*)&hs1[sk * HS_S + 4 * srp]     = dupf(h1a);
            *(ull*)&hs1[sk * HS_S + 4 * srp + 2] = dupf(h1b);
        }
        __syncthreads();

        // ---- three FMA passes (one matrix each, 4 packed accumulators) ----
        const float* hp0 = hs0 + ks * 16 * HS_S;
        const float* hp1 = hs1 + ks * 16 * HS_S;
        float* pbase = ps + ks * PS_S + 2 * lane;
#pragma unroll
        for (int m = 0; m < 3; ++m) {
            const ull*   wr = (m == 0) ? wr0 : (m == 1) ? wr1 : wr2;
            const float* hp = (m == 2) ? hp1 : hp0;
            ull a0 = 0, a1 = 0, a2 = 0, a3 = 0;
#pragma unroll
            for (int kk = 0; kk < 16; ++kk) {
                ulonglong2 ha = *(const ulonglong2*)(hp + kk * HS_S);      // b0,b1
                ulonglong2 hb = *(const ulonglong2*)(hp + kk * HS_S + 4);  // b2,b3
                ull w = wr[kk];
                a0 = ffma2(ha.x, w, a0);
                a1 = ffma2(ha.y, w, a1);
                a2 = ffma2(hb.x, w, a2);
                a3 = ffma2(hb.y, w, a3);
            }
            float* pb = pbase + m * 16 * PS_S;
            *(ull*)&pb[0]   = a0;
            *(ull*)&pb[64]  = a1;
            *(ull*)&pb[128] = a2;
            *(ull*)&pb[192] = a3;
        }
        __syncthreads();

        // ---- k-split reduce (packed) + epilogue ----
        if (egrp < 3) {
            const int m = (egrp == 0) ? 0 : (egrp == 1) ? 2 : 1;
            const float* pr = ps + m * 16 * PS_S + eb * 64 + 2 * ejp;
            ull s = 0;
#pragma unroll
            for (int p = 0; p < 16; ++p)
                s = ffma2(*(const ull*)(pr + p * PS_S), one2, s);

            const int row = bg + eb;
            if (egrp == 0) {                         // G0: h0n[t]
                if (t < Sz) {
                    float2 sv = asf2(s), av = asf2(a0p);
                    float2 v = make_float2(tanhf(sv.x + av.x), tanhf(sv.y + av.y));
                    *(float2*)&g_h0r[t & 1][row * 256 + co] = v;
                    if (t == Sz - 1) *(float2*)&hf[(row * 2 + 0) * 256 + co] = v;
                }
            } else if (egrp == 2) {                  // G1: a1[t-1] (local)
                if (t >= 1 && t <= Sz) {
                    float2 sv = asf2(s), bvv = asf2(bias2);
                    *(float2*)&a1s[((t - 1) & 1) * 256 + eidx * 2] =
                        make_float2(sv.x + bvv.x, sv.y + bvv.y);
                }
            } else {                                 // G2: h1n[t-2]
                if (t >= 2) {
                    float2 sv = asf2(s);
                    float2 a1v = *(const float2*)&a1s[(t & 1) * 256 + eidx * 2];
                    float2 v = make_float2(tanhf(sv.x + a1v.x), tanhf(sv.y + a1v.y));
                    if (t <= Sz) *(float2*)&g_h1r[t & 1][row * 256 + co] = v;
                    *(float2*)&g_H1[((size_t)row * Sz + (t - 2)) * 256 + co] = v;
                    if (t == Sz + 1) *(float2*)&hf[(row * 2 + 1) * 256 + co] = v;
                }
            }
        }

        // ---- one cluster barrier per step (orders ring STG -> next LDG,
        //      doubles as CTA-wide sync for ps/a1s reuse) ----
        asm volatile("barrier.cluster.arrive.aligned;" ::: "memory");
        asm volatile("barrier.cluster.wait.aligned;" ::: "memory");
    }
}

// ---------------- launch ----------------------------------------------------
extern "C" void kernel_launch(void* const* d_in, const int* in_sizes, int n_in,
                              void* d_out, int out_size) {
    const float* x    = (const float*)d_in[0];
    const float* w_h0 = (const float*)d_in[1];
    const float* u_h0 = (const float*)d_in[2];
    const float* b_h0 = (const float*)d_in[3];
    const float* w_h1 = (const float*)d_in[4];
    const float* u_h1 = (const float*)d_in[5];
    const float* b_h1 = (const float*)d_in[6];
    const float* w_q  = (const float*)d_in[7];
    const float* b_q  = (const float*)d_in[8];

    float* out = (float*)d_out;                       // [B,S,O]
    float* hf  = out + (size_t)Bz * Sz * Hz;          // [B,2,H]

    float *pA0 = nullptr, *pH1 = nullptr;
    cudaGetSymbolAddress((void**)&pA0, g_A0);
    cudaGetSymbolAddress((void**)&pH1, g_H1);

    const int smem_bytes = (2 * 256 * HS_S + 3 * 16 * PS_S + 2 * 256) * 4; // 77312
    cudaFuncSetAttribute(rnn_k, cudaFuncAttributeMaxDynamicSharedMemorySize, smem_bytes);

    init_k<<<128, 256>>>();
    gemm256<<<dim3((Bz * Sz) / 64, 4), 256>>>(x, w_h0, b_h0, pA0);
    rnn_k<<<64, 512, smem_bytes>>>(u_h0, w_h1, u_h1, b_h1, hf);
    gemm256<<<dim3((Bz * Sz) / 64, 4), 256>>>(pH1, w_q, b_q, out);
}

// round 9
// speedup vs baseline: 1.3567x; 1.3567x over previous
#include <cuda_runtime.h>
#include <cstdint>
#include <cstddef>

#define Bz 64
#define Sz 2048
#define Hz 256
#define PS 392   // partial row stride (floats), 384 used

typedef unsigned long long ull;

// ---------------- scratch (static device arrays: no runtime allocation) -----
__device__ float g_A0[(size_t)Bz * Sz * Hz];   // x@w_h0 + b_h0, [B,S,H]
__device__ float g_H1[(size_t)Bz * Sz * Hz];   // h1 states,     [B,S,H]
__device__ float g_h0r[2][Bz * Hz];            // h0 state ring  [slot][b*256+k]
__device__ float g_h1r[2][Bz * Hz];            // h1 state ring

// packed fp32x2 ops (sm_100+)
__device__ __forceinline__ ull ffma2(ull a, ull b, ull c) {
    ull d;
    asm("fma.rn.f32x2 %0, %1, %2, %3;" : "=l"(d) : "l"(a), "l"(b), "l"(c));
    return d;
}
__device__ __forceinline__ ull dupf(float x) {
    ull r;
    asm("mov.b64 %0, {%1, %1};" : "=l"(r) : "f"(x));
    return r;
}
__device__ __forceinline__ float2 asf2(ull u) {
    float2 f;
    asm("mov.b64 {%0, %1}, %2;" : "=f"(f.x), "=f"(f.y) : "l"(u));
    return f;
}
__device__ __forceinline__ uint32_t smem_u32(const void* p) {
    return (uint32_t)__cvta_generic_to_shared(p);
}
__device__ __forceinline__ void mbar_wait_acq(uint32_t mbar, uint32_t parity) {
    asm volatile(
        "{\n\t"
        ".reg .pred P;\n\t"
        "WLP_%=:\n\t"
        "mbarrier.try_wait.parity.acquire.cluster.shared::cta.b64 P, [%0], %1;\n\t"
        "@!P bra WLP_%=;\n\t"
        "}\n\t"
        :: "r"(mbar), "r"(parity) : "memory");
}
__device__ __forceinline__ void mbar_arrive_rel(uint32_t mbar_local, int rank) {
    uint32_t rm;
    asm("mapa.shared::cluster.u32 %0, %1, %2;" : "=r"(rm) : "r"(mbar_local), "r"(rank));
    asm volatile("mbarrier.arrive.release.cluster.shared::cluster.b64 _, [%0];"
                 :: "r"(rm) : "memory");
}

// ---------------- init: zero state rings each launch (determinism) ----------
__global__ void init_k() {
    int i = blockIdx.x * blockDim.x + threadIdx.x;
    if (i < 2 * Bz * Hz) {
        ((float*)g_h0r)[i] = 0.f;
        ((float*)g_h1r)[i] = 0.f;
    }
}

// ---------------- C[M,256] = A[M,256] @ W[256,256] + bias -------------------
// 128x128 tile, 256 threads, 8x8 outputs/thread (split row/col halves so all
// LDS.128 phases are conflict-free). 1.0 B/MAC from smem -> FMA-pipe bound.
__global__ __launch_bounds__(256) void gemm256(const float* __restrict__ A,
                                               const float* __restrict__ W,
                                               const float* __restrict__ bias,
                                               float* __restrict__ C) {
    __shared__ float As[32][132];   // [k][m] transposed A chunk
    __shared__ float Ws[32][132];   // [k][n] W chunk
    const int tid = threadIdx.x;
    const int tm = tid >> 4;        // 0..15  -> rows tm*4.. and 64+tm*4..
    const int tn = tid & 15;        // 0..15  -> cols tn*4.. and 64+tn*4..
    const int m0 = blockIdx.x * 128, n0 = blockIdx.y * 128;

    const int am = tid >> 1;              // A stage: row
    const int ak = (tid & 1) * 16;        // A stage: k-half
    const int wk = tid >> 3;              // W stage: k row
    const int wn = (tid & 7) * 4;         // W stage: col group

    ull acc[8][4];
#pragma unroll
    for (int r = 0; r < 8; ++r)
#pragma unroll
        for (int c = 0; c < 4; ++c) acc[r][c] = 0ull;

    for (int k0 = 0; k0 < 256; k0 += 32) {
#pragma unroll
        for (int q = 0; q < 4; ++q) {
            float4 f = *(const float4*)&A[(size_t)(m0 + am) * 256 + k0 + ak + q * 4];
            As[ak + q * 4 + 0][am] = f.x;
            As[ak + q * 4 + 1][am] = f.y;
            As[ak + q * 4 + 2][am] = f.z;
            As[ak + q * 4 + 3][am] = f.w;
        }
#pragma unroll
        for (int q = 0; q < 4; ++q)
            *(float4*)&Ws[wk][q * 32 + wn] =
                *(const float4*)&W[(size_t)(k0 + wk) * 256 + n0 + q * 32 + wn];
        __syncthreads();

#pragma unroll 8
        for (int k = 0; k < 32; ++k) {
            float4 a0 = *(const float4*)&As[k][tm * 4];
            float4 a1 = *(const float4*)&As[k][64 + tm * 4];
            ulonglong2 w0 = *(const ulonglong2*)&Ws[k][tn * 4];
            ulonglong2 w1 = *(const ulonglong2*)&Ws[k][64 + tn * 4];
            float av[8] = {a0.x, a0.y, a0.z, a0.w, a1.x, a1.y, a1.z, a1.w};
#pragma unroll
            for (int r = 0; r < 8; ++r) {
                ull d = dupf(av[r]);
                acc[r][0] = ffma2(d, w0.x, acc[r][0]);
                acc[r][1] = ffma2(d, w0.y, acc[r][1]);
                acc[r][2] = ffma2(d, w1.x, acc[r][2]);
                acc[r][3] = ffma2(d, w1.y, acc[r][3]);
            }
        }
        __syncthreads();
    }

    const float4 bv0 = *(const float4*)&bias[n0 + tn * 4];
    const float4 bv1 = *(const float4*)&bias[n0 + 64 + tn * 4];
#pragma unroll
    for (int r = 0; r < 8; ++r) {
        int row = m0 + ((r < 4) ? tm * 4 + r : 64 + tm * 4 + (r - 4));
        float2 p0 = asf2(acc[r][0]), p1 = asf2(acc[r][1]);
        float2 p2 = asf2(acc[r][2]), p3 = asf2(acc[r][3]);
        *(float4*)&C[(size_t)row * 256 + n0 + tn * 4] =
            make_float4(p0.x + bv0.x, p0.y + bv0.y, p1.x + bv0.z, p1.y + bv0.w);
        *(float4*)&C[(size_t)row * 256 + n0 + 64 + tn * 4] =
            make_float4(p2.x + bv1.x, p2.y + bv1.y, p3.x + bv1.z, p3.y + bv1.w);
    }
}

// ---------------- persistent clustered recurrence (R5 + mbar + packed) ------
// 32 clusters x 4 CTAs x 512 threads. Cluster g owns batch rows {2g, 2g+1};
// CTA rank r owns columns [64r, 64r+64) of u_h0/w_h1/u_h1 (in REGISTERS).
// Exchange via L2 rings; per-step sync = 4-arrive mbarrier rendezvous.
// Pipeline: G0 h0n[t]; G1 a1[t-1] (local smem); G2 h1n[t-2].
__global__ void __cluster_dims__(4, 1, 1) __launch_bounds__(512, 1)
rnn_k(const float* __restrict__ u_h0, const float* __restrict__ w_h1,
      const float* __restrict__ u_h1, const float* __restrict__ b_h1,
      float* __restrict__ hf) {
    __shared__ float hs0[1024];         // dup state: hs0[k*4+2b] = (h0,h0)
    __shared__ float hs1[1024];
    __shared__ float ps[16 * PS];       // k-split partials
    __shared__ float a1s[2 * 128];      // local a1 ring
    __shared__ ull   mbar;

    const int tid = threadIdx.x;
    const int ks  = tid >> 5;                 // warp id = k-split (16)
    const int jg  = tid & 31;                 // lane = j-pair
    const int bg  = (blockIdx.x >> 2) * 2;    // first batch row of cluster
    const int j0  = (blockIdx.x & 3) * 64;    // first col of this CTA

    // ---- persistent weights in registers: 3 x 16 packed col-pairs ----
    ull wr0[16], wr1[16], wr2[16];
#pragma unroll
    for (int kk = 0; kk < 16; ++kk) {
        size_t o = (size_t)(ks * 16 + kk) * 256 + j0 + jg * 2;
        wr0[kk] = __ldg((const ull*)&u_h0[o]);
        wr1[kk] = __ldg((const ull*)&w_h1[o]);
        wr2[kk] = __ldg((const ull*)&u_h1[o]);
    }

    const uint32_t mbar_u = smem_u32(&mbar);
    if (tid == 0)
        asm volatile("mbarrier.init.shared.b64 [%0], %1;" :: "r"(mbar_u), "r"(4) : "memory");
    __syncthreads();
    asm volatile("barrier.cluster.arrive.aligned;" ::: "memory");
    asm volatile("barrier.cluster.wait.aligned;" ::: "memory");

    // packed reduce/epilogue identity: eg 0:h0n 1:h1n 2:a1, 3..7 idle
    const int eg   = tid >> 6;
    const int eidx = tid & 63;
    const int eb   = eidx >> 5;               // row 0/1
    const int ejp  = eidx & 31;               // col pair
    const int co   = j0 + ejp * 2;
    ull bias2 = 0;
    if (eg == 2) bias2 = *(const ull*)&b_h1[co];
    const ull one2 = dupf(1.0f);

    // stage identity: sb = row (0/1), sk = k
    const int sb = tid >> 8, sk = tid & 255;

    for (int t = 0; t < Sz + 2; ++t) {
        // A0 prefetch for G0 epilogue (issued before the rendezvous wait)
        ull a0p = 0;
        if (eg == 0 && t < Sz)
            a0p = __ldcg((const ull*)&g_A0[((size_t)(bg + eb) * Sz + t) * 256 + co]);

        // rendezvous: step-(t-1) ring publishes from all CTAs now visible
        if (t > 0) mbar_wait_acq(mbar_u, (t - 1) & 1);

        // ---- stage states from L2 rings into duplicated smem ----
        {
            const int sl = (t + 1) & 1;       // h0n[t-1] / h1n[t-3] parity
            float v0 = __ldcg(&g_h0r[sl][(bg + sb) * 256 + sk]);
            float v1 = __ldcg(&g_h1r[sl][(bg + sb) * 256 + sk]);
            *(ull*)&hs0[sk * 4 + 2 * sb] = dupf(v0);
            *(ull*)&hs1[sk * 4 + 2 * sb] = dupf(v1);
        }
        __syncthreads();

        // ---- main: 3 GEMM partials, weights in regs, broadcast LDS ----
        ull a00 = 0, a01 = 0, a10 = 0, a11 = 0, a20 = 0, a21 = 0;
        {
            const float* h0p = &hs0[ks * 64];
            const float* h1p = &hs1[ks * 64];
#pragma unroll
            for (int kk = 0; kk < 16; ++kk) {
                ulonglong2 h0 = *(const ulonglong2*)(h0p + kk * 4);
                ulonglong2 h1 = *(const ulonglong2*)(h1p + kk * 4);
                a00 = ffma2(h0.x, wr0[kk], a00);
                a01 = ffma2(h0.y, wr0[kk], a01);
                a10 = ffma2(h0.x, wr1[kk], a10);
                a11 = ffma2(h0.y, wr1[kk], a11);
                a20 = ffma2(h1.x, wr2[kk], a20);
                a21 = ffma2(h1.y, wr2[kk], a21);
            }
        }
        // store k-split partials: ps[ks][m*128 + b*64 + jg*2]
        {
            float* pb = ps + ks * PS + jg * 2;
            *(ull*)&pb[0]   = a00;  *(ull*)&pb[64]  = a01;
            *(ull*)&pb[128] = a10;  *(ull*)&pb[192] = a11;
            *(ull*)&pb[256] = a20;  *(ull*)&pb[320] = a21;
        }
        __syncthreads();

        // ---- packed k-split reduce + epilogue ----
        if (eg < 3) {
            const int m = (eg == 0) ? 0 : (eg == 1) ? 2 : 1;
            const float* pr = ps + m * 128 + eb * 64 + ejp * 2;
            ull s = 0;
#pragma unroll
            for (int p = 0; p < 16; ++p)
                s = ffma2(*(const ull*)(pr + p * PS), one2, s);

            const int row = bg + eb;
            if (eg == 0) {                           // G0: h0n[t]
                if (t < Sz) {
                    float2 sv = asf2(s), av = asf2(a0p);
                    float2 v = make_float2(tanhf(sv.x + av.x), tanhf(sv.y + av.y));
                    *(float2*)&g_h0r[t & 1][row * 256 + co] = v;
                    if (t == Sz - 1) *(float2*)&hf[(row * 2 + 0) * 256 + co] = v;
                }
            } else if (eg == 2) {                    // G1: a1[t-1] (local)
                if (t >= 1 && t <= Sz) {
                    float2 sv = asf2(s), bvv = asf2(bias2);
                    *(float2*)&a1s[((t - 1) & 1) * 128 + eb * 64 + ejp * 2] =
                        make_float2(sv.x + bvv.x, sv.y + bvv.y);
                }
            } else {                                 // G2: h1n[t-2]
                if (t >= 2) {
                    float2 sv = asf2(s);
                    float2 a1v = *(const float2*)&a1s[(t & 1) * 128 + eb * 64 + ejp * 2];
                    float2 v = make_float2(tanhf(sv.x + a1v.x), tanhf(sv.y + a1v.y));
                    if (t <= Sz) *(float2*)&g_h1r[t & 1][row * 256 + co] = v;
                    *(float2*)&g_H1[((size_t)row * Sz + (t - 2)) * 256 + co] = v;
                    if (t == Sz + 1) *(float2*)&hf[(row * 2 + 1) * 256 + co] = v;
                }
            }
        }
        __syncthreads();                  // all publishes issued CTA-wide

        // release-arrive on every cluster CTA's mbarrier (threads 0..3)
        if (t <= Sz && tid < 4) mbar_arrive_rel(mbar_u, tid);
    }

    // straggler guard: remote arrives must land before any CTA exits
    asm volatile("barrier.cluster.arrive.aligned;" ::: "memory");
    asm volatile("barrier.cluster.wait.aligned;" ::: "memory");
}

// ---------------- launch ----------------------------------------------------
extern "C" void kernel_launch(void* const* d_in, const int* in_sizes, int n_in,
                              void* d_out, int out_size) {
    const float* x    = (const float*)d_in[0];
    const float* w_h0 = (const float*)d_in[1];
    const float* u_h0 = (const float*)d_in[2];
    const float* b_h0 = (const float*)d_in[3];
    const float* w_h1 = (const float*)d_in[4];
    const float* u_h1 = (const float*)d_in[5];
    const float* b_h1 = (const float*)d_in[6];
    const float* w_q  = (const float*)d_in[7];
    const float* b_q  = (const float*)d_in[8];

    float* out = (float*)d_out;                       // [B,S,O]
    float* hf  = out + (size_t)Bz * Sz * Hz;          // [B,2,H]

    float *pA0 = nullptr, *pH1 = nullptr;
    cudaGetSymbolAddress((void**)&pA0, g_A0);
    cudaGetSymbolAddress((void**)&pH1, g_H1);

    init_k<<<128, 256>>>();
    gemm256<<<dim3((Bz * Sz) / 128, 2), 256>>>(x, w_h0, b_h0, pA0);
    rnn_k<<<128, 512>>>(u_h0, w_h1, u_h1, b_h1, hf);
    gemm256<<<dim3((Bz * Sz) / 128, 2), 256>>>(pH1, w_q, b_q, out);
}

// round 10
// speedup vs baseline: 1.5344x; 1.1310x over previous
#include <cuda_runtime.h>
#include <cstdint>
#include <cstddef>

#define Bz 64
#define Sz 2048
#define Hz 256
#define PS 392   // partial row stride (floats), 384 used

typedef unsigned long long ull;

// ---------------- scratch (static device arrays: no runtime allocation) -----
__device__ float g_A0[(size_t)Bz * Sz * Hz];   // x@w_h0 + b_h0, [B,S,H]
__device__ float g_H1[(size_t)Bz * Sz * Hz];   // h1 states,     [B,S,H]
__device__ float g_h0r[2][Bz * Hz];            // h0 state ring  [slot][b*256+k]
__device__ float g_h1r[2][Bz * Hz];            // h1 state ring

// packed fp32x2 ops (sm_100+)
__device__ __forceinline__ ull ffma2(ull a, ull b, ull c) {
    ull d;
    asm("fma.rn.f32x2 %0, %1, %2, %3;" : "=l"(d) : "l"(a), "l"(b), "l"(c));
    return d;
}
__device__ __forceinline__ ull dupf(float x) {
    ull r;
    asm("mov.b64 %0, {%1, %1};" : "=l"(r) : "f"(x));
    return r;
}
__device__ __forceinline__ float2 asf2(ull u) {
    float2 f;
    asm("mov.b64 {%0, %1}, %2;" : "=f"(f.x), "=f"(f.y) : "l"(u));
    return f;
}

// ---------------- init: zero state rings each launch (determinism) ----------
__global__ void init_k() {
    int i = blockIdx.x * blockDim.x + threadIdx.x;
    if (i < 2 * Bz * Hz) {
        ((float*)g_h0r)[i] = 0.f;
        ((float*)g_h1r)[i] = 0.f;
    }
}

// ---------------- C[M,256] = A[M,256] @ W[256,256] + bias -------------------
// 128x128 tile, 256 threads, 8x8 outputs/thread (split row/col halves so all
// LDS.128 phases are conflict-free). 1.0 B/MAC from smem -> FMA-pipe bound.
// __launch_bounds__(256,2): two CTAs per SM to hide __syncthreads bubbles.
__global__ __launch_bounds__(256, 2) void gemm256(const float* __restrict__ A,
                                                  const float* __restrict__ W,
                                                  const float* __restrict__ bias,
                                                  float* __restrict__ C) {
    __shared__ float As[32][132];   // [k][m] transposed A chunk
    __shared__ float Ws[32][132];   // [k][n] W chunk
    const int tid = threadIdx.x;
    const int tm = tid >> 4;        // 0..15  -> rows tm*4.. and 64+tm*4..
    const int tn = tid & 15;        // 0..15  -> cols tn*4.. and 64+tn*4..
    const int m0 = blockIdx.x * 128, n0 = blockIdx.y * 128;

    const int am = tid >> 1;              // A stage: row
    const int ak = (tid & 1) * 16;        // A stage: k-half
    const int wk = tid >> 3;              // W stage: k row
    const int wn = (tid & 7) * 4;         // W stage: col group

    ull acc[8][4];
#pragma unroll
    for (int r = 0; r < 8; ++r)
#pragma unroll
        for (int c = 0; c < 4; ++c) acc[r][c] = 0ull;

    for (int k0 = 0; k0 < 256; k0 += 32) {
#pragma unroll
        for (int q = 0; q < 4; ++q) {
            float4 f = *(const float4*)&A[(size_t)(m0 + am) * 256 + k0 + ak + q * 4];
            As[ak + q * 4 + 0][am] = f.x;
            As[ak + q * 4 + 1][am] = f.y;
            As[ak + q * 4 + 2][am] = f.z;
            As[ak + q * 4 + 3][am] = f.w;
        }
#pragma unroll
        for (int q = 0; q < 4; ++q)
            *(float4*)&Ws[wk][q * 32 + wn] =
                *(const float4*)&W[(size_t)(k0 + wk) * 256 + n0 + q * 32 + wn];
        __syncthreads();

#pragma unroll 8
        for (int k = 0; k < 32; ++k) {
            float4 a0 = *(const float4*)&As[k][tm * 4];
            float4 a1 = *(const float4*)&As[k][64 + tm * 4];
            ulonglong2 w0 = *(const ulonglong2*)&Ws[k][tn * 4];
            ulonglong2 w1 = *(const ulonglong2*)&Ws[k][64 + tn * 4];
            float av[8] = {a0.x, a0.y, a0.z, a0.w, a1.x, a1.y, a1.z, a1.w};
#pragma unroll
            for (int r = 0; r < 8; ++r) {
                ull d = dupf(av[r]);
                acc[r][0] = ffma2(d, w0.x, acc[r][0]);
                acc[r][1] = ffma2(d, w0.y, acc[r][1]);
                acc[r][2] = ffma2(d, w1.x, acc[r][2]);
                acc[r][3] = ffma2(d, w1.y, acc[r][3]);
            }
        }
        __syncthreads();
    }

    const float4 bv0 = *(const float4*)&bias[n0 + tn * 4];
    const float4 bv1 = *(const float4*)&bias[n0 + 64 + tn * 4];
#pragma unroll
    for (int r = 0; r < 8; ++r) {
        int row = m0 + ((r < 4) ? tm * 4 + r : 64 + tm * 4 + (r - 4));
        float2 p0 = asf2(acc[r][0]), p1 = asf2(acc[r][1]);
        float2 p2 = asf2(acc[r][2]), p3 = asf2(acc[r][3]);
        *(float4*)&C[(size_t)row * 256 + n0 + tn * 4] =
            make_float4(p0.x + bv0.x, p0.y + bv0.y, p1.x + bv0.z, p1.y + bv0.w);
        *(float4*)&C[(size_t)row * 256 + n0 + 64 + tn * 4] =
            make_float4(p2.x + bv1.x, p2.y + bv1.y, p3.x + bv1.z, p3.y + bv1.w);
    }
}

// ---------------- persistent clustered recurrence (R5 verbatim) -------------
// 32 clusters x 4 CTAs x 512 threads. Cluster g owns batch rows {2g, 2g+1};
// CTA rank r owns columns [64r, 64r+64) of u_h0 / w_h1 / u_h1 (in REGISTERS).
// State exchange via L2 rings; one barrier.cluster per step.
// Pipeline: G0 h0n[t]; G1 a1[t-1] (local smem); G2 h1n[t-2].
__global__ void __cluster_dims__(4, 1, 1) __launch_bounds__(512, 1)
rnn_k(const float* __restrict__ u_h0, const float* __restrict__ w_h1,
      const float* __restrict__ u_h1, const float* __restrict__ b_h1,
      float* __restrict__ hf) {
    __shared__ float hs0[1024];         // dup state: hs0[k*4+2b] = (h0,h0)
    __shared__ float hs1[1024];
    __shared__ float ps[16 * PS];       // k-split partials
    __shared__ float a1s[2 * 128];      // local a1 ring

    const int tid = threadIdx.x;
    const int ks  = tid >> 5;                 // warp id = k-split (16)
    const int jg  = tid & 31;                 // lane = j-group (2 cols)
    const int bg  = (blockIdx.x >> 2) * 2;    // first batch row of cluster
    const int j0  = (blockIdx.x & 3) * 64;    // first col of this CTA

    // ---- persistent weights in registers: 3 x 16 packed col-pairs ----
    ull wr0[16], wr1[16], wr2[16];
#pragma unroll
    for (int kk = 0; kk < 16; ++kk) {
        size_t o = (size_t)(ks * 16 + kk) * 256 + j0 + jg * 2;
        wr0[kk] = __ldg((const ull*)&u_h0[o]);
        wr1[kk] = __ldg((const ull*)&w_h1[o]);
        wr2[kk] = __ldg((const ull*)&u_h1[o]);
    }

    // epilogue identity: threads [0,384): o = m*128 + b*64 + j
    const int eo = tid;
    const int em = eo >> 7;
    const int er = eo & 127;
    const int eb = er >> 6;
    const int ej = er & 63;
    const float bias = b_h1[j0 + ej];

    // stage identity: thread -> (b = tid>>8, k = tid&255)
    const int sb = tid >> 8, sk = tid & 255;

    for (int t = 0; t < Sz + 2; ++t) {
        // A0 prefetch for G0 epilogue (L2/DRAM, hidden behind the step)
        float a0v = 0.f;
        if (em == 0 && eo < 128 && t < Sz)
            a0v = __ldcg(&g_A0[((size_t)(bg + eb) * Sz + t) * 256 + j0 + ej]);

        // ---- stage states from L2 rings into duplicated smem ----
        {
            const int sl = (t + 1) & 1;       // h0n[t-1] / h1n[t-3] parity
            float v0 = __ldcg(&g_h0r[sl][(bg + sb) * 256 + sk]);
            float v1 = __ldcg(&g_h1r[sl][(bg + sb) * 256 + sk]);
            *(ull*)&hs0[sk * 4 + 2 * sb] = dupf(v0);
            *(ull*)&hs1[sk * 4 + 2 * sb] = dupf(v1);
        }
        __syncthreads();

        // ---- main: 3 GEMM partials, weights from regs, states broadcast ----
        ull a00 = 0, a01 = 0, a10 = 0, a11 = 0, a20 = 0, a21 = 0;
        {
            const float* h0p = &hs0[ks * 64];   // 16 k-rows * 4 floats
            const float* h1p = &hs1[ks * 64];
#pragma unroll
            for (int kk = 0; kk < 16; ++kk) {
                ulonglong2 h0 = *(const ulonglong2*)(h0p + kk * 4);
                ulonglong2 h1 = *(const ulonglong2*)(h1p + kk * 4);
                a00 = ffma2(h0.x, wr0[kk], a00);
                a01 = ffma2(h0.y, wr0[kk], a01);
                a10 = ffma2(h0.x, wr1[kk], a10);
                a11 = ffma2(h0.y, wr1[kk], a11);
                a20 = ffma2(h1.x, wr2[kk], a20);
                a21 = ffma2(h1.y, wr2[kk], a21);
            }
        }
        // store k-split partials: ps[ks][m*128 + b*64 + jg*2]
        {
            float* pb = ps + ks * PS + jg * 2;
            *(ull*)&pb[0]   = a00;  *(ull*)&pb[64]  = a01;
            *(ull*)&pb[128] = a10;  *(ull*)&pb[192] = a11;
            *(ull*)&pb[256] = a20;  *(ull*)&pb[320] = a21;
        }
        __syncthreads();

        // ---- reduce 16 partials + epilogue ----
        if (eo < 384) {
            float s = 0.f;
#pragma unroll
            for (int p = 0; p < 16; ++p) s += ps[p * PS + eo];

            const int gofs = (bg + eb) * 256 + j0 + ej;
            if (em == 0) {
                if (t < Sz) {
                    float v = tanhf(s + a0v);
                    g_h0r[t & 1][gofs] = v;
                    if (t == Sz - 1) hf[((bg + eb) * 2 + 0) * 256 + j0 + ej] = v;
                }
            } else if (em == 1) {
                if (t >= 1 && t <= Sz)
                    a1s[((t - 1) & 1) * 128 + er] = s + bias;   // a1[t-1]
            } else {
                if (t >= 2) {
                    float v = tanhf(s + a1s[(t & 1) * 128 + er]); // + a1[t-2]
                    if (t <= Sz) g_h1r[t & 1][gofs] = v;
                    g_H1[((size_t)(bg + eb) * Sz + (t - 2)) * 256 + j0 + ej] = v;
                    if (t == Sz + 1) hf[((bg + eb) * 2 + 1) * 256 + j0 + ej] = v;
                }
            }
        }

        // ---- one cluster barrier per step (orders ring STG -> next LDG) ----
        asm volatile("barrier.cluster.arrive.aligned;" ::: "memory");
        asm volatile("barrier.cluster.wait.aligned;" ::: "memory");
    }
}

// ---------------- launch ----------------------------------------------------
extern "C" void kernel_launch(void* const* d_in, const int* in_sizes, int n_in,
                              void* d_out, int out_size) {
    const float* x    = (const float*)d_in[0];
    const float* w_h0 = (const float*)d_in[1];
    const float* u_h0 = (const float*)d_in[2];
    const float* b_h0 = (const float*)d_in[3];
    const float* w_h1 = (const float*)d_in[4];
    const float* u_h1 = (const float*)d_in[5];
    const float* b_h1 = (const float*)d_in[6];
    const float* w_q  = (const float*)d_in[7];
    const float* b_q  = (const float*)d_in[8];

    float* out = (float*)d_out;                       // [B,S,O]
    float* hf  = out + (size_t)Bz * Sz * Hz;          // [B,2,H]

    float *pA0 = nullptr, *pH1 = nullptr;
    cudaGetSymbolAddress((void**)&pA0, g_A0);
    cudaGetSymbolAddress((void**)&pH1, g_H1);

    init_k<<<128, 256>>>();
    gemm256<<<dim3((Bz * Sz) / 128, 2), 256>>>(x, w_h0, b_h0, pA0);
    rnn_k<<<128, 512>>>(u_h0, w_h1, u_h1, b_h1, hf);
    gemm256<<<dim3((Bz * Sz) / 128, 2), 256>>>(pH1, w_q, b_q, out);
}